// round 1
// baseline (speedup 1.0000x reference)
#include <cuda_runtime.h>
#include <cuda_bf16.h>
#include <math.h>

// ---------------------------------------------------------------------------
// Problem constants
// ---------------------------------------------------------------------------
constexpr int B_  = 16;
constexpr int T_  = 2356;   // M + N*L
constexpr int E_  = 768;
constexpr int H_  = 12;
constexpr int D_  = 64;     // head dim
constexpr int M_  = 4;      // CLS tokens
constexpr int N_  = 12;     // frames
constexpr int L_  = 196;    // tokens per frame
constexpr int BH_ = B_ * H_;          // 192
constexpr int MTOT = B_ * T_;         // 37696
constexpr int KEYS = M_ + L_;         // 200 keys per frame window

// ---------------------------------------------------------------------------
// Scratch (device globals: no cudaMalloc allowed)
// ---------------------------------------------------------------------------
__device__ float g_q[(size_t)BH_ * T_ * D_];     // (BH, T, d), pre-scaled
__device__ float g_k[(size_t)BH_ * T_ * D_];
__device__ float g_v[(size_t)BH_ * T_ * D_];
__device__ float g_attn[(size_t)B_ * T_ * E_];   // (B, T, E) pre-Wo

// ---------------------------------------------------------------------------
// SGEMM:  C = A(MTOT x 768) @ W(768 x 768) + bias, optional scale.
// MODE 0: write permuted to (BH, T, d) layout (for q/k/v)
// MODE 1: write row-major (MTOT, 768)      (for output proj)
// 128x128x16 tile, 256 threads, 8x8 per-thread microtile.
// ---------------------------------------------------------------------------
template <int MODE>
__global__ __launch_bounds__(256) void sgemm_kernel(
    const float* __restrict__ A, const float* __restrict__ W,
    const float* __restrict__ bias, float* __restrict__ C, float scale)
{
    __shared__ float As[16][128];   // transposed: As[k][m]
    __shared__ float Bs[16][128];

    const int blockM = blockIdx.x;
    const int blockN = blockIdx.y;
    const int tid = threadIdx.x;
    const int ty = tid >> 4;        // 0..15
    const int tx = tid & 15;        // 0..15

    // load mappings
    const int aRow = tid >> 2;           // 0..63
    const int aCol = (tid & 3) * 4;      // 0,4,8,12
    const int bRow = tid >> 5;           // 0..7
    const int bCol = (tid & 31) * 4;     // 0..124

    float acc[8][8];
#pragma unroll
    for (int i = 0; i < 8; i++)
#pragma unroll
        for (int j = 0; j < 8; j++) acc[i][j] = 0.f;

    for (int k0 = 0; k0 < 768; k0 += 16) {
        // --- load A tile (128x16), transposed into As[k][m]
#pragma unroll
        for (int r = 0; r < 2; r++) {
            int row = blockM * 128 + aRow + r * 64;
            float4 a = make_float4(0.f, 0.f, 0.f, 0.f);
            if (row < MTOT)
                a = *(const float4*)(A + (size_t)row * 768 + k0 + aCol);
            As[aCol + 0][aRow + r * 64] = a.x;
            As[aCol + 1][aRow + r * 64] = a.y;
            As[aCol + 2][aRow + r * 64] = a.z;
            As[aCol + 3][aRow + r * 64] = a.w;
        }
        // --- load B tile (16x128)
#pragma unroll
        for (int r = 0; r < 2; r++) {
            int kk = bRow + r * 8;
            *(float4*)&Bs[kk][bCol] =
                *(const float4*)(W + (size_t)(k0 + kk) * 768 + blockN * 128 + bCol);
        }
        __syncthreads();

#pragma unroll
        for (int kk = 0; kk < 16; kk++) {
            float af[8], bf[8];
            *(float4*)(af)     = *(const float4*)&As[kk][ty * 8];
            *(float4*)(af + 4) = *(const float4*)&As[kk][ty * 8 + 4];
            *(float4*)(bf)     = *(const float4*)&Bs[kk][tx * 8];
            *(float4*)(bf + 4) = *(const float4*)&Bs[kk][tx * 8 + 4];
#pragma unroll
            for (int i = 0; i < 8; i++)
#pragma unroll
                for (int j = 0; j < 8; j++)
                    acc[i][j] = fmaf(af[i], bf[j], acc[i][j]);
        }
        __syncthreads();
    }

    // --- epilogue
#pragma unroll
    for (int i = 0; i < 8; i++) {
        int row = blockM * 128 + ty * 8 + i;
        if (row >= MTOT) continue;
        int b = row / T_;
        int t = row - b * T_;
#pragma unroll
        for (int j = 0; j < 8; j++) {
            int col = blockN * 128 + tx * 8 + j;
            float val = (acc[i][j] + bias[col]) * scale;
            if (MODE == 0) {
                int h  = col >> 6;
                int dd = col & 63;
                C[(((size_t)(b * H_ + h)) * T_ + t) * D_ + dd] = val;
            } else {
                C[(size_t)row * 768 + col] = val;
            }
        }
    }
}

// ---------------------------------------------------------------------------
// Frame attention: one block per (bh, n) window.
// 196 queries x 200 keys x d=64.  K,V staged in smem (stride 65 for
// conflict-free column access). 16 warps; each warp processes 4 queries at a
// time, each lane owns up to 7 keys (lane + 32*j).
// ---------------------------------------------------------------------------
constexpr int FA_WARPS = 16;
constexpr int FA_THREADS = FA_WARPS * 32;
constexpr int KV_STRIDE = 65;
constexpr int FA_SMEM_FLOATS =
    KEYS * KV_STRIDE * 2 + FA_WARPS * 4 * KEYS + FA_WARPS * 4 * D_;
constexpr int FA_SMEM_BYTES = FA_SMEM_FLOATS * 4;

__global__ __launch_bounds__(FA_THREADS) void frame_attn_kernel(
    const float* __restrict__ q, const float* __restrict__ k,
    const float* __restrict__ v, float* __restrict__ out)
{
    extern __shared__ float sm[];
    float* Ks = sm;                               // [200][65]
    float* Vs = Ks + KEYS * KV_STRIDE;            // [200][65]
    float* Ps = Vs + KEYS * KV_STRIDE;            // [16][4][200]
    float* Qs = Ps + FA_WARPS * 4 * KEYS;         // [16][4][64]

    const int blk = blockIdx.x;
    const int bh  = blk / N_;
    const int n   = blk - bh * N_;
    const int b   = bh / H_;
    const int h   = bh - b * H_;

    const float* qb = q + (size_t)bh * T_ * D_;
    const float* kb = k + (size_t)bh * T_ * D_;
    const float* vb = v + (size_t)bh * T_ * D_;

    // stage K, V
    for (int idx = threadIdx.x; idx < KEYS * D_; idx += FA_THREADS) {
        int key = idx >> 6;
        int dim = idx & 63;
        int t = (key < M_) ? key : (M_ + n * L_ + key - M_);
        Ks[key * KV_STRIDE + dim] = kb[(size_t)t * D_ + dim];
        Vs[key * KV_STRIDE + dim] = vb[(size_t)t * D_ + dim];
    }
    __syncthreads();

    const int warp = threadIdx.x >> 5;
    const int lane = threadIdx.x & 31;

    int koff[7];
    bool kval[7];
#pragma unroll
    for (int j = 0; j < 7; j++) {
        int key = lane + 32 * j;
        kval[j] = (key < KEYS);
        koff[j] = (kval[j] ? key : 0) * KV_STRIDE;
    }

    for (int g = warp; g < L_ / 4; g += FA_WARPS) {   // 49 query groups of 4
        const int q0 = g * 4;
        // stage 4 query vectors for this warp
#pragma unroll
        for (int r = 0; r < 8; r++) {
            int idx = lane + r * 32;                  // 0..255
            int qi  = idx >> 6;
            int dim = idx & 63;
            Qs[(warp * 4 + qi) * D_ + dim] =
                qb[(size_t)(M_ + n * L_ + q0 + qi) * D_ + dim];
        }
        __syncwarp();

        // QK^T: s[qi][j]
        float s[4][7];
#pragma unroll
        for (int qi = 0; qi < 4; qi++)
#pragma unroll
            for (int j = 0; j < 7; j++) s[qi][j] = 0.f;

#pragma unroll 4
        for (int dim = 0; dim < D_; dim++) {
            float kv[7];
#pragma unroll
            for (int j = 0; j < 7; j++) kv[j] = Ks[koff[j] + dim];
            float qv[4];
#pragma unroll
            for (int qi = 0; qi < 4; qi++) qv[qi] = Qs[(warp * 4 + qi) * D_ + dim];
#pragma unroll
            for (int qi = 0; qi < 4; qi++)
#pragma unroll
                for (int j = 0; j < 7; j++)
                    s[qi][j] = fmaf(qv[qi], kv[j], s[qi][j]);
        }

        // softmax per query (warp-wide over 200 keys)
        float invs[4];
#pragma unroll
        for (int qi = 0; qi < 4; qi++) {
            float mx = -1e30f;
#pragma unroll
            for (int j = 0; j < 7; j++)
                if (kval[j]) mx = fmaxf(mx, s[qi][j]);
#pragma unroll
            for (int o = 16; o; o >>= 1)
                mx = fmaxf(mx, __shfl_xor_sync(0xffffffffu, mx, o));
            float sum = 0.f;
#pragma unroll
            for (int j = 0; j < 7; j++) {
                float p = kval[j] ? __expf(s[qi][j] - mx) : 0.f;
                s[qi][j] = p;
                sum += p;
            }
#pragma unroll
            for (int o = 16; o; o >>= 1)
                sum += __shfl_xor_sync(0xffffffffu, sum, o);
            invs[qi] = 1.f / sum;
#pragma unroll
            for (int j = 0; j < 7; j++)
                if (kval[j]) Ps[(warp * 4 + qi) * KEYS + lane + 32 * j] = s[qi][j];
        }
        __syncwarp();

        // PV: each lane accumulates dims {lane, lane+32} for 4 queries
        float o0[4] = {0.f, 0.f, 0.f, 0.f};
        float o1[4] = {0.f, 0.f, 0.f, 0.f};
#pragma unroll 4
        for (int key = 0; key < KEYS; key++) {
            float v0 = Vs[key * KV_STRIDE + lane];
            float v1 = Vs[key * KV_STRIDE + lane + 32];
#pragma unroll
            for (int qi = 0; qi < 4; qi++) {
                float p = Ps[(warp * 4 + qi) * KEYS + key];
                o0[qi] = fmaf(p, v0, o0[qi]);
                o1[qi] = fmaf(p, v1, o1[qi]);
            }
        }
#pragma unroll
        for (int qi = 0; qi < 4; qi++) {
            int t = M_ + n * L_ + q0 + qi;
            float* dst = out + ((size_t)b * T_ + t) * E_ + h * D_;
            dst[lane]      = o0[qi] * invs[qi];
            dst[lane + 32] = o1[qi] * invs[qi];
        }
        __syncwarp();
    }
}

// ---------------------------------------------------------------------------
// CLS attention: one block per bh. 4 queries x 2356 keys. Scores in smem.
// ---------------------------------------------------------------------------
__global__ __launch_bounds__(256) void cls_attn_kernel(
    const float* __restrict__ q, const float* __restrict__ k,
    const float* __restrict__ v, float* __restrict__ out)
{
    __shared__ float Qs[M_ * D_];         // 4 x 64
    __shared__ float S[M_ * T_];          // 4 x 2356 scores
    __shared__ float inv_sum[M_];

    const int bh = blockIdx.x;
    const int b  = bh / H_;
    const int h  = bh - b * H_;
    const int tid = threadIdx.x;

    const float* qb = q + (size_t)bh * T_ * D_;
    const float* kb = k + (size_t)bh * T_ * D_;
    const float* vb = v + (size_t)bh * T_ * D_;

    Qs[tid] = qb[tid];   // 256 threads cover 4*64 exactly
    __syncthreads();

    // scores
    for (int key = tid; key < T_; key += 256) {
        const float4* kp = (const float4*)(kb + (size_t)key * D_);
        float s0 = 0.f, s1 = 0.f, s2 = 0.f, s3 = 0.f;
#pragma unroll
        for (int c = 0; c < 16; c++) {
            float4 kv = kp[c];
            int base = c * 4;
            s0 += Qs[0 * D_ + base] * kv.x + Qs[0 * D_ + base + 1] * kv.y +
                  Qs[0 * D_ + base + 2] * kv.z + Qs[0 * D_ + base + 3] * kv.w;
            s1 += Qs[1 * D_ + base] * kv.x + Qs[1 * D_ + base + 1] * kv.y +
                  Qs[1 * D_ + base + 2] * kv.z + Qs[1 * D_ + base + 3] * kv.w;
            s2 += Qs[2 * D_ + base] * kv.x + Qs[2 * D_ + base + 1] * kv.y +
                  Qs[2 * D_ + base + 2] * kv.z + Qs[2 * D_ + base + 3] * kv.w;
            s3 += Qs[3 * D_ + base] * kv.x + Qs[3 * D_ + base + 1] * kv.y +
                  Qs[3 * D_ + base + 2] * kv.z + Qs[3 * D_ + base + 3] * kv.w;
        }
        S[0 * T_ + key] = s0;
        S[1 * T_ + key] = s1;
        S[2 * T_ + key] = s2;
        S[3 * T_ + key] = s3;
    }
    __syncthreads();

    // softmax: warps 0..3 handle queries 0..3
    const int warp = tid >> 5, lane = tid & 31;
    if (warp < M_) {
        const int m = warp;
        float mx = -1e30f;
        for (int i = lane; i < T_; i += 32) mx = fmaxf(mx, S[m * T_ + i]);
#pragma unroll
        for (int o = 16; o; o >>= 1)
            mx = fmaxf(mx, __shfl_xor_sync(0xffffffffu, mx, o));
        float sum = 0.f;
        for (int i = lane; i < T_; i += 32) {
            float e = __expf(S[m * T_ + i] - mx);
            S[m * T_ + i] = e;
            sum += e;
        }
#pragma unroll
        for (int o = 16; o; o >>= 1)
            sum += __shfl_xor_sync(0xffffffffu, sum, o);
        if (lane == 0) inv_sum[m] = 1.f / sum;
    }
    __syncthreads();

    // PV: thread = (m, dim)
    const int m = tid >> 6;
    const int dim = tid & 63;
    float acc = 0.f;
#pragma unroll 8
    for (int key = 0; key < T_; key++)
        acc = fmaf(S[m * T_ + key], vb[(size_t)key * D_ + dim], acc);
    out[((size_t)b * T_ + m) * E_ + h * D_ + dim] = acc * inv_sum[m];
}

// ---------------------------------------------------------------------------
// launch
// ---------------------------------------------------------------------------
extern "C" void kernel_launch(void* const* d_in, const int* in_sizes, int n_in,
                              void* d_out, int out_size)
{
    const float* hs = (const float*)d_in[0];
    const float* Wq = (const float*)d_in[1];
    const float* bq = (const float*)d_in[2];
    const float* Wk = (const float*)d_in[3];
    const float* bk = (const float*)d_in[4];
    const float* Wv = (const float*)d_in[5];
    const float* bv = (const float*)d_in[6];
    const float* Wo = (const float*)d_in[7];
    const float* bo = (const float*)d_in[8];
    float* out = (float*)d_out;

    float *gq, *gk, *gv, *gattn;
    cudaGetSymbolAddress((void**)&gq, g_q);
    cudaGetSymbolAddress((void**)&gk, g_k);
    cudaGetSymbolAddress((void**)&gv, g_v);
    cudaGetSymbolAddress((void**)&gattn, g_attn);

    const dim3 ggrid((MTOT + 127) / 128, E_ / 128);
    const dim3 gblk(256);

    // QKV projections (q pre-scaled by d^-0.5)
    sgemm_kernel<0><<<ggrid, gblk>>>(hs, Wq, bq, gq, 0.125f);
    sgemm_kernel<0><<<ggrid, gblk>>>(hs, Wk, bk, gk, 1.0f);
    sgemm_kernel<0><<<ggrid, gblk>>>(hs, Wv, bv, gv, 1.0f);

    // attention
    cudaFuncSetAttribute(frame_attn_kernel,
                         cudaFuncAttributeMaxDynamicSharedMemorySize,
                         FA_SMEM_BYTES);
    frame_attn_kernel<<<BH_ * N_, FA_THREADS, FA_SMEM_BYTES>>>(gq, gk, gv, gattn);
    cls_attn_kernel<<<BH_, 256>>>(gq, gk, gv, gattn);

    // output projection
    sgemm_kernel<1><<<ggrid, gblk>>>(gattn, Wo, bo, out, 1.0f);
}

// round 4
// speedup vs baseline: 1.9418x; 1.9418x over previous
#include <cuda_runtime.h>
#include <cuda_bf16.h>
#include <math.h>
#include <stdint.h>

// ---------------------------------------------------------------------------
// Problem constants
// ---------------------------------------------------------------------------
constexpr int B_  = 16;
constexpr int T_  = 2356;   // M + N*L
constexpr int E_  = 768;
constexpr int H_  = 12;
constexpr int D_  = 64;     // head dim
constexpr int M_  = 4;      // CLS tokens
constexpr int N_  = 12;     // frames
constexpr int L_  = 196;    // tokens per frame
constexpr int BH_ = B_ * H_;          // 192
constexpr int MTOT = B_ * T_;         // 37696
constexpr int KEYS = M_ + L_;         // 200 keys per frame window

// ---------------------------------------------------------------------------
// Scratch (device globals: no cudaMalloc allowed)
// ---------------------------------------------------------------------------
__device__ float g_q[(size_t)BH_ * T_ * D_];     // (BH, T, d), pre-scaled
__device__ float g_k[(size_t)BH_ * T_ * D_];
__device__ float g_v[(size_t)BH_ * T_ * D_];
__device__ float g_attn[(size_t)B_ * T_ * E_];   // (B, T, E) pre-Wo

// ---------------------------------------------------------------------------
// TF32 tensor-core GEMM:  C = A(MTOT x 768) @ W(768 x 768) + bias, * scale.
// MODE 0: write permuted to (BH, T, d) layout (for q/k/v)
// MODE 1: write row-major (MTOT, 768)      (for output proj)
//
// Block tile 128x128x32, 256 threads (8 warps), warp tile 64x32
// (warps arranged 2 x 4). mma.sync.m16n8k8.tf32, fp32 accumulate.
// Double-buffered smem + register prefetch of the next K-slice.
// Smem layouts chosen for conflict-free fragment loads:
//   As[m][k]  stride 36  -> a-frag bank = (4g + q)  : unique over warp
//   Bs[k][n]  stride 136 -> b-frag bank = (8q + g)  : unique over warp
// ---------------------------------------------------------------------------
constexpr int GM_BM = 128;
constexpr int GM_BN = 128;
constexpr int GM_BK = 32;
constexpr int AS_STRIDE = 36;    // floats per A row
constexpr int BS_STRIDE = 136;   // floats per B row
constexpr int AS_FLOATS = GM_BM * AS_STRIDE;       // 4608
constexpr int BS_FLOATS = GM_BK * BS_STRIDE;       // 4352
constexpr int GM_SMEM_FLOATS = 2 * (AS_FLOATS + BS_FLOATS);
constexpr int GM_SMEM_BYTES  = GM_SMEM_FLOATS * 4; // 71680

__device__ __forceinline__ uint32_t f2tf32(float x) {
    uint32_t u;
    asm("cvt.rna.tf32.f32 %0, %1;" : "=r"(u) : "f"(x));
    return u;
}

__device__ __forceinline__ void mma_tf32(float c[4], const uint32_t a[4],
                                         const uint32_t b[2]) {
    asm volatile(
        "mma.sync.aligned.m16n8k8.row.col.f32.tf32.tf32.f32 "
        "{%0,%1,%2,%3}, {%4,%5,%6,%7}, {%8,%9}, {%0,%1,%2,%3};\n"
        : "+f"(c[0]), "+f"(c[1]), "+f"(c[2]), "+f"(c[3])
        : "r"(a[0]), "r"(a[1]), "r"(a[2]), "r"(a[3]), "r"(b[0]), "r"(b[1]));
}

template <int MODE>
__global__ __launch_bounds__(256, 1) void gemm_tf32_kernel(
    const float* __restrict__ A, const float* __restrict__ W,
    const float* __restrict__ bias, float* __restrict__ C, float scale)
{
    extern __shared__ float sm[];
    float* As = sm;                         // [2][128][36]
    float* Bs = sm + 2 * AS_FLOATS;         // [2][32][136]

    const int tid  = threadIdx.x;
    const int warp = tid >> 5;
    const int lane = tid & 31;
    const int g = lane >> 2;                // group id 0..7
    const int q = lane & 3;                 // thread-in-group 0..3
    const int warp_m = warp >> 2;           // 0..1  (64-row slab)
    const int warp_n = warp & 3;            // 0..3  (32-col slab)

    const int blockM = blockIdx.x;
    const int blockN = blockIdx.y;

    // global-load mappings
    const int arow0 = tid >> 3;             // 0..31
    const int acol  = (tid & 7) * 4;        // k offset 0..28
    const int brow0 = tid >> 5;             // 0..7
    const int bcol  = (tid & 31) * 4;       // n offset 0..124

    float acc[4][4][4];
#pragma unroll
    for (int i = 0; i < 4; i++)
#pragma unroll
        for (int j = 0; j < 4; j++)
#pragma unroll
            for (int r = 0; r < 4; r++) acc[i][j][r] = 0.f;

    float ra[4][4];   // A prefetch: 4 rows x float4
    float rb[4][4];   // B prefetch: 4 k-rows x float4

    auto load_tile = [&](int k0) {
#pragma unroll
        for (int r = 0; r < 4; r++) {
            int row = blockM * GM_BM + arow0 + r * 32;
            float4 v = make_float4(0.f, 0.f, 0.f, 0.f);
            if (row < MTOT)
                v = *(const float4*)(A + (size_t)row * E_ + k0 + acol);
            ra[r][0] = v.x; ra[r][1] = v.y; ra[r][2] = v.z; ra[r][3] = v.w;
        }
#pragma unroll
        for (int r = 0; r < 4; r++) {
            int kk = brow0 + r * 8;
            float4 v = *(const float4*)(W + (size_t)(k0 + kk) * E_
                                        + blockN * GM_BN + bcol);
            rb[r][0] = v.x; rb[r][1] = v.y; rb[r][2] = v.z; rb[r][3] = v.w;
        }
    };

    auto store_tile = [&](int buf) {
        float* as = As + buf * AS_FLOATS;
        float* bs = Bs + buf * BS_FLOATS;
#pragma unroll
        for (int r = 0; r < 4; r++) {
            float4 v;
            v.x = __uint_as_float(f2tf32(ra[r][0]));
            v.y = __uint_as_float(f2tf32(ra[r][1]));
            v.z = __uint_as_float(f2tf32(ra[r][2]));
            v.w = __uint_as_float(f2tf32(ra[r][3]));
            *(float4*)(as + (arow0 + r * 32) * AS_STRIDE + acol) = v;
        }
#pragma unroll
        for (int r = 0; r < 4; r++) {
            float4 v;
            v.x = __uint_as_float(f2tf32(rb[r][0]));
            v.y = __uint_as_float(f2tf32(rb[r][1]));
            v.z = __uint_as_float(f2tf32(rb[r][2]));
            v.w = __uint_as_float(f2tf32(rb[r][3]));
            *(float4*)(bs + (brow0 + r * 8) * BS_STRIDE + bcol) = v;
        }
    };

    load_tile(0);
    store_tile(0);
    __syncthreads();

    constexpr int NITER = E_ / GM_BK;       // 24
    for (int it = 0; it < NITER; ++it) {
        if (it + 1 < NITER) load_tile((it + 1) * GM_BK);

        const uint32_t* as = (const uint32_t*)(As + (it & 1) * AS_FLOATS);
        const uint32_t* bs = (const uint32_t*)(Bs + (it & 1) * BS_FLOATS);

#pragma unroll
        for (int kk = 0; kk < 4; kk++) {
            const int k0 = kk * 8;
            uint32_t af[4][4];
#pragma unroll
            for (int mt = 0; mt < 4; mt++) {
                int base = (warp_m * 64 + mt * 16 + g) * AS_STRIDE + k0 + q;
                af[mt][0] = as[base];
                af[mt][1] = as[base + 8 * AS_STRIDE];
                af[mt][2] = as[base + 4];
                af[mt][3] = as[base + 8 * AS_STRIDE + 4];
            }
            uint32_t bf[4][2];
#pragma unroll
            for (int nt = 0; nt < 4; nt++) {
                int base = (k0 + q) * BS_STRIDE + warp_n * 32 + nt * 8 + g;
                bf[nt][0] = bs[base];
                bf[nt][1] = bs[base + 4 * BS_STRIDE];
            }
#pragma unroll
            for (int mt = 0; mt < 4; mt++)
#pragma unroll
                for (int nt = 0; nt < 4; nt++)
                    mma_tf32(acc[mt][nt], af[mt], bf[nt]);
        }

        if (it + 1 < NITER) {
            store_tile((it + 1) & 1);
            __syncthreads();
        }
    }

    // ---- epilogue
#pragma unroll
    for (int mt = 0; mt < 4; mt++) {
#pragma unroll
        for (int half = 0; half < 2; half++) {
            int row = blockM * GM_BM + warp_m * 64 + mt * 16 + g + half * 8;
            if (row >= MTOT) continue;
            int b = row / T_;
            int t = row - b * T_;
#pragma unroll
            for (int nt = 0; nt < 4; nt++) {
                int col = blockN * GM_BN + warp_n * 32 + nt * 8 + q * 2;
                float v0 = (acc[mt][nt][half * 2 + 0] + bias[col]) * scale;
                float v1 = (acc[mt][nt][half * 2 + 1] + bias[col + 1]) * scale;
                if (MODE == 0) {
                    int h  = col >> 6;
                    int dd = col & 63;
                    float2* dst = (float2*)(C +
                        (((size_t)(b * H_ + h)) * T_ + t) * D_ + dd);
                    *dst = make_float2(v0, v1);
                } else {
                    *(float2*)(C + (size_t)row * E_ + col) = make_float2(v0, v1);
                }
            }
        }
    }
}

// ---------------------------------------------------------------------------
// Frame attention: one block per (bh, n) window.
// ---------------------------------------------------------------------------
constexpr int FA_WARPS = 16;
constexpr int FA_THREADS = FA_WARPS * 32;
constexpr int KV_STRIDE = 65;
constexpr int FA_SMEM_FLOATS =
    KEYS * KV_STRIDE * 2 + FA_WARPS * 4 * KEYS + FA_WARPS * 4 * D_;
constexpr int FA_SMEM_BYTES = FA_SMEM_FLOATS * 4;

__global__ __launch_bounds__(FA_THREADS) void frame_attn_kernel(
    const float* __restrict__ q, const float* __restrict__ k,
    const float* __restrict__ v, float* __restrict__ out)
{
    extern __shared__ float sm[];
    float* Ks = sm;                               // [200][65]
    float* Vs = Ks + KEYS * KV_STRIDE;            // [200][65]
    float* Ps = Vs + KEYS * KV_STRIDE;            // [16][4][200]
    float* Qs = Ps + FA_WARPS * 4 * KEYS;         // [16][4][64]

    const int blk = blockIdx.x;
    const int bh  = blk / N_;
    const int n   = blk - bh * N_;
    const int b   = bh / H_;
    const int h   = bh - b * H_;

    const float* qb = q + (size_t)bh * T_ * D_;
    const float* kb = k + (size_t)bh * T_ * D_;
    const float* vb = v + (size_t)bh * T_ * D_;

    for (int idx = threadIdx.x; idx < KEYS * D_; idx += FA_THREADS) {
        int key = idx >> 6;
        int dim = idx & 63;
        int t = (key < M_) ? key : (M_ + n * L_ + key - M_);
        Ks[key * KV_STRIDE + dim] = kb[(size_t)t * D_ + dim];
        Vs[key * KV_STRIDE + dim] = vb[(size_t)t * D_ + dim];
    }
    __syncthreads();

    const int warp = threadIdx.x >> 5;
    const int lane = threadIdx.x & 31;

    int koff[7];
    bool kval[7];
#pragma unroll
    for (int j = 0; j < 7; j++) {
        int key = lane + 32 * j;
        kval[j] = (key < KEYS);
        koff[j] = (kval[j] ? key : 0) * KV_STRIDE;
    }

    for (int g = warp; g < L_ / 4; g += FA_WARPS) {
        const int q0 = g * 4;
#pragma unroll
        for (int r = 0; r < 8; r++) {
            int idx = lane + r * 32;
            int qi  = idx >> 6;
            int dim = idx & 63;
            Qs[(warp * 4 + qi) * D_ + dim] =
                qb[(size_t)(M_ + n * L_ + q0 + qi) * D_ + dim];
        }
        __syncwarp();

        float s[4][7];
#pragma unroll
        for (int qi = 0; qi < 4; qi++)
#pragma unroll
            for (int j = 0; j < 7; j++) s[qi][j] = 0.f;

#pragma unroll 4
        for (int dim = 0; dim < D_; dim++) {
            float kv[7];
#pragma unroll
            for (int j = 0; j < 7; j++) kv[j] = Ks[koff[j] + dim];
            float qv[4];
#pragma unroll
            for (int qi = 0; qi < 4; qi++) qv[qi] = Qs[(warp * 4 + qi) * D_ + dim];
#pragma unroll
            for (int qi = 0; qi < 4; qi++)
#pragma unroll
                for (int j = 0; j < 7; j++)
                    s[qi][j] = fmaf(qv[qi], kv[j], s[qi][j]);
        }

        float invs[4];
#pragma unroll
        for (int qi = 0; qi < 4; qi++) {
            float mx = -1e30f;
#pragma unroll
            for (int j = 0; j < 7; j++)
                if (kval[j]) mx = fmaxf(mx, s[qi][j]);
#pragma unroll
            for (int o = 16; o; o >>= 1)
                mx = fmaxf(mx, __shfl_xor_sync(0xffffffffu, mx, o));
            float sum = 0.f;
#pragma unroll
            for (int j = 0; j < 7; j++) {
                float p = kval[j] ? __expf(s[qi][j] - mx) : 0.f;
                s[qi][j] = p;
                sum += p;
            }
#pragma unroll
            for (int o = 16; o; o >>= 1)
                sum += __shfl_xor_sync(0xffffffffu, sum, o);
            invs[qi] = 1.f / sum;
#pragma unroll
            for (int j = 0; j < 7; j++)
                if (kval[j]) Ps[(warp * 4 + qi) * KEYS + lane + 32 * j] = s[qi][j];
        }
        __syncwarp();

        float o0[4] = {0.f, 0.f, 0.f, 0.f};
        float o1[4] = {0.f, 0.f, 0.f, 0.f};
#pragma unroll 4
        for (int key = 0; key < KEYS; key++) {
            float v0 = Vs[key * KV_STRIDE + lane];
            float v1 = Vs[key * KV_STRIDE + lane + 32];
#pragma unroll
            for (int qi = 0; qi < 4; qi++) {
                float p = Ps[(warp * 4 + qi) * KEYS + key];
                o0[qi] = fmaf(p, v0, o0[qi]);
                o1[qi] = fmaf(p, v1, o1[qi]);
            }
        }
#pragma unroll
        for (int qi = 0; qi < 4; qi++) {
            int t = M_ + n * L_ + q0 + qi;
            float* dst = out + ((size_t)b * T_ + t) * E_ + h * D_;
            dst[lane]      = o0[qi] * invs[qi];
            dst[lane + 32] = o1[qi] * invs[qi];
        }
        __syncwarp();
    }
}

// ---------------------------------------------------------------------------
// CLS attention
// ---------------------------------------------------------------------------
__global__ __launch_bounds__(256) void cls_attn_kernel(
    const float* __restrict__ q, const float* __restrict__ k,
    const float* __restrict__ v, float* __restrict__ out)
{
    __shared__ float Qs[M_ * D_];
    __shared__ float S[M_ * T_];
    __shared__ float inv_sum[M_];

    const int bh = blockIdx.x;
    const int b  = bh / H_;
    const int h  = bh - b * H_;
    const int tid = threadIdx.x;

    const float* qb = q + (size_t)bh * T_ * D_;
    const float* kb = k + (size_t)bh * T_ * D_;
    const float* vb = v + (size_t)bh * T_ * D_;

    Qs[tid] = qb[tid];
    __syncthreads();

    for (int key = tid; key < T_; key += 256) {
        const float4* kp = (const float4*)(kb + (size_t)key * D_);
        float s0 = 0.f, s1 = 0.f, s2 = 0.f, s3 = 0.f;
#pragma unroll
        for (int c = 0; c < 16; c++) {
            float4 kv = kp[c];
            int base = c * 4;
            s0 += Qs[0 * D_ + base] * kv.x + Qs[0 * D_ + base + 1] * kv.y +
                  Qs[0 * D_ + base + 2] * kv.z + Qs[0 * D_ + base + 3] * kv.w;
            s1 += Qs[1 * D_ + base] * kv.x + Qs[1 * D_ + base + 1] * kv.y +
                  Qs[1 * D_ + base + 2] * kv.z + Qs[1 * D_ + base + 3] * kv.w;
            s2 += Qs[2 * D_ + base] * kv.x + Qs[2 * D_ + base + 1] * kv.y +
                  Qs[2 * D_ + base + 2] * kv.z + Qs[2 * D_ + base + 3] * kv.w;
            s3 += Qs[3 * D_ + base] * kv.x + Qs[3 * D_ + base + 1] * kv.y +
                  Qs[3 * D_ + base + 2] * kv.z + Qs[3 * D_ + base + 3] * kv.w;
        }
        S[0 * T_ + key] = s0;
        S[1 * T_ + key] = s1;
        S[2 * T_ + key] = s2;
        S[3 * T_ + key] = s3;
    }
    __syncthreads();

    const int warp = tid >> 5, lane = tid & 31;
    if (warp < M_) {
        const int m = warp;
        float mx = -1e30f;
        for (int i = lane; i < T_; i += 32) mx = fmaxf(mx, S[m * T_ + i]);
#pragma unroll
        for (int o = 16; o; o >>= 1)
            mx = fmaxf(mx, __shfl_xor_sync(0xffffffffu, mx, o));
        float sum = 0.f;
        for (int i = lane; i < T_; i += 32) {
            float e = __expf(S[m * T_ + i] - mx);
            S[m * T_ + i] = e;
            sum += e;
        }
#pragma unroll
        for (int o = 16; o; o >>= 1)
            sum += __shfl_xor_sync(0xffffffffu, sum, o);
        if (lane == 0) inv_sum[m] = 1.f / sum;
    }
    __syncthreads();

    const int m = tid >> 6;
    const int dim = tid & 63;
    float acc = 0.f;
#pragma unroll 8
    for (int key = 0; key < T_; key++)
        acc = fmaf(S[m * T_ + key], vb[(size_t)key * D_ + dim], acc);
    out[((size_t)b * T_ + m) * E_ + h * D_ + dim] = acc * inv_sum[m];
}

// ---------------------------------------------------------------------------
// launch
// ---------------------------------------------------------------------------
extern "C" void kernel_launch(void* const* d_in, const int* in_sizes, int n_in,
                              void* d_out, int out_size)
{
    const float* hs = (const float*)d_in[0];
    const float* Wq = (const float*)d_in[1];
    const float* bq = (const float*)d_in[2];
    const float* Wk = (const float*)d_in[3];
    const float* bk = (const float*)d_in[4];
    const float* Wv = (const float*)d_in[5];
    const float* bv = (const float*)d_in[6];
    const float* Wo = (const float*)d_in[7];
    const float* bo = (const float*)d_in[8];
    float* out = (float*)d_out;

    float *gq, *gk, *gv, *gattn;
    cudaGetSymbolAddress((void**)&gq, g_q);
    cudaGetSymbolAddress((void**)&gk, g_k);
    cudaGetSymbolAddress((void**)&gv, g_v);
    cudaGetSymbolAddress((void**)&gattn, g_attn);

    cudaFuncSetAttribute(gemm_tf32_kernel<0>,
                         cudaFuncAttributeMaxDynamicSharedMemorySize,
                         GM_SMEM_BYTES);
    cudaFuncSetAttribute(gemm_tf32_kernel<1>,
                         cudaFuncAttributeMaxDynamicSharedMemorySize,
                         GM_SMEM_BYTES);
    cudaFuncSetAttribute(frame_attn_kernel,
                         cudaFuncAttributeMaxDynamicSharedMemorySize,
                         FA_SMEM_BYTES);

    const dim3 ggrid((MTOT + GM_BM - 1) / GM_BM, E_ / GM_BN);
    const dim3 gblk(256);

    // QKV projections (q pre-scaled by d^-0.5)
    gemm_tf32_kernel<0><<<ggrid, gblk, GM_SMEM_BYTES>>>(hs, Wq, bq, gq, 0.125f);
    gemm_tf32_kernel<0><<<ggrid, gblk, GM_SMEM_BYTES>>>(hs, Wk, bk, gk, 1.0f);
    gemm_tf32_kernel<0><<<ggrid, gblk, GM_SMEM_BYTES>>>(hs, Wv, bv, gv, 1.0f);

    // attention
    frame_attn_kernel<<<BH_ * N_, FA_THREADS, FA_SMEM_BYTES>>>(gq, gk, gv, gattn);
    cls_attn_kernel<<<BH_, 256>>>(gq, gk, gv, gattn);

    // output projection
    gemm_tf32_kernel<1><<<ggrid, gblk, GM_SMEM_BYTES>>>(gattn, Wo, bo, out, 1.0f);
}